// round 7
// baseline (speedup 1.0000x reference)
#include <cuda_runtime.h>
#include <math.h>

#define BATCH 2
#define SEQ   2048
#define CDIM  1024
#define HEADS 16
#define HD    64
#define SCALE 0.125f
#define LOG2E 1.44269504088896f

#define BHN   (BATCH*HEADS)
#define ROWS  (BATCH*SEQ)
#define QKVN  (3*CDIM)

// tf32 Q (pre-scaled by SCALE*LOG2E), K, V in (B,H,N,D)
__device__ unsigned g_Qt[BATCH*HEADS*SEQ*HD];
__device__ unsigned g_Kt[BATCH*HEADS*SEQ*HD];
__device__ unsigned g_Vt[BATCH*HEADS*SEQ*HD];
__device__ float    g_att_fallback[ROWS*CDIM];

__device__ __forceinline__ unsigned f2tf32(float x) {
    unsigned u;
    asm("cvt.rna.tf32.f32 %0, %1;" : "=r"(u) : "f"(x));
    return u;
}

__device__ __forceinline__ void mma_tf32(float* d,
                                         unsigned a0, unsigned a1, unsigned a2, unsigned a3,
                                         unsigned b0, unsigned b1) {
    asm volatile(
        "mma.sync.aligned.m16n8k8.row.col.f32.tf32.tf32.f32 "
        "{%0,%1,%2,%3}, {%4,%5,%6,%7}, {%8,%9}, {%0,%1,%2,%3};"
        : "+f"(d[0]), "+f"(d[1]), "+f"(d[2]), "+f"(d[3])
        : "r"(a0), "r"(a1), "r"(a2), "r"(a3), "r"(b0), "r"(b1));
}

#define AST 20    // A smem row stride ([m][k] layout): banks 20g+t conflict-free
#define BST 136   // B smem row stride ([k][n] layout): banks 8t+g conflict-free

// ---------------------------------------------------------------------------
// Kernel 1: QKV GEMM. 128x128 tile, BK=16, reg-prefetch double buffer.
// A stored [m][k] (STS.128 conflict-free), B stored [k][n].
// ---------------------------------------------------------------------------
__global__ __launch_bounds__(128, 2) void qkv_tc(const float* __restrict__ X,
                                                 const float* __restrict__ W) {
    __shared__ unsigned sA[2][128][AST];
    __shared__ unsigned sB[2][16][BST];

    const int tid = threadIdx.x;
    const int lane = tid & 31;
    const int w = tid >> 5;
    const int g = lane >> 2, t = lane & 3;
    const int wm = w & 1, wn = w >> 1;

    const int m0 = blockIdx.y * 128;
    const int n0 = blockIdx.x * 128;

    float acc[4][8][4];
#pragma unroll
    for (int mt = 0; mt < 4; mt++)
#pragma unroll
        for (int nt = 0; nt < 8; nt++)
#pragma unroll
            for (int i = 0; i < 4; i++) acc[mt][nt][i] = 0.f;

    // A: thread -> row tid, 4 float4 chunks along k
    const float* aptr = X + (size_t)(m0 + tid) * CDIM;
    // B: thread -> rows (tid>>5)+4i, col 4*(tid&31)
    const int bk = tid >> 5, bn = 4 * (tid & 31);
    const float* bptr = W + (size_t)bk * QKVN + n0 + bn;

    float4 ra[4], rb[4];
#pragma unroll
    for (int i = 0; i < 4; i++) {
        ra[i] = *(const float4*)(aptr + 4 * i);
        rb[i] = *(const float4*)(bptr + (size_t)(4 * i) * QKVN);
    }

    int buf = 0;
#pragma unroll
    for (int i = 0; i < 4; i++) {
        *(uint4*)&sA[0][tid][4 * i] = make_uint4(f2tf32(ra[i].x), f2tf32(ra[i].y),
                                                 f2tf32(ra[i].z), f2tf32(ra[i].w));
        *(uint4*)&sB[0][bk + 4 * i][bn] = make_uint4(f2tf32(rb[i].x), f2tf32(rb[i].y),
                                                     f2tf32(rb[i].z), f2tf32(rb[i].w));
    }
    __syncthreads();

    for (int k0 = 16; k0 <= CDIM; k0 += 16) {
        if (k0 < CDIM) {
#pragma unroll
            for (int i = 0; i < 4; i++) {
                ra[i] = *(const float4*)(aptr + k0 + 4 * i);
                rb[i] = *(const float4*)(bptr + (size_t)(k0 + 4 * i) * QKVN);
            }
        }

#pragma unroll
        for (int kt = 0; kt < 2; kt++) {
            unsigned af[4][4];
#pragma unroll
            for (int mt = 0; mt < 4; mt++) {
                int mr = wm * 64 + mt * 16;
                af[mt][0] = sA[buf][mr + g][8 * kt + t];
                af[mt][1] = sA[buf][mr + g + 8][8 * kt + t];
                af[mt][2] = sA[buf][mr + g][8 * kt + t + 4];
                af[mt][3] = sA[buf][mr + g + 8][8 * kt + t + 4];
            }
#pragma unroll
            for (int nt = 0; nt < 8; nt++) {
                int nc = wn * 64 + nt * 8 + g;
                unsigned b0 = sB[buf][kt * 8 + t][nc];
                unsigned b1 = sB[buf][kt * 8 + t + 4][nc];
#pragma unroll
                for (int mt = 0; mt < 4; mt++)
                    mma_tf32(acc[mt][nt], af[mt][0], af[mt][1], af[mt][2], af[mt][3], b0, b1);
            }
        }

        if (k0 < CDIM) {
#pragma unroll
            for (int i = 0; i < 4; i++) {
                *(uint4*)&sA[buf ^ 1][tid][4 * i] =
                    make_uint4(f2tf32(ra[i].x), f2tf32(ra[i].y),
                               f2tf32(ra[i].z), f2tf32(ra[i].w));
                *(uint4*)&sB[buf ^ 1][bk + 4 * i][bn] =
                    make_uint4(f2tf32(rb[i].x), f2tf32(rb[i].y),
                               f2tf32(rb[i].z), f2tf32(rb[i].w));
            }
            __syncthreads();
            buf ^= 1;
        }
    }

    // scatter epilogue -> tf32 (Q pre-scaled)
    const float QF = SCALE * LOG2E;
#pragma unroll
    for (int mt = 0; mt < 4; mt++) {
#pragma unroll
        for (int nt = 0; nt < 8; nt++) {
            int col = n0 + wn * 64 + nt * 8 + 2 * t;
            int s = col >> 10;
            int h = (col >> 6) & 15;
            int dd = col & 63;
            unsigned* dst = (s == 0) ? g_Qt : (s == 1) ? g_Kt : g_Vt;
            float sc = (s == 0) ? QF : 1.f;
            int row0 = m0 + wm * 64 + mt * 16 + g;
#pragma unroll
            for (int half = 0; half < 2; half++) {
                int row = row0 + 8 * half;
                int b = row >> 11, n = row & 2047;
                unsigned* p = dst + ((((size_t)b * HEADS + h) * SEQ + n) * HD + dd);
                *(uint2*)p = make_uint2(f2tf32(acc[mt][nt][2 * half] * sc),
                                        f2tf32(acc[mt][nt][2 * half + 1] * sc));
            }
        }
    }
}

// ---------------------------------------------------------------------------
// Kernel 2: flash attention; 32 query rows per warp (2 row-groups), so each
// K/V fragment pair feeds 2 mmas. Block = 128 threads = 128 query rows.
// ---------------------------------------------------------------------------
#define SKS 68
#define SVS 72
#define SPS 68
#define FLASH_SMEM ((64*SKS + 64*SVS + 128*SPS) * 4)

__global__ __launch_bounds__(128) void flash_attn_tc(float* __restrict__ out2) {
    extern __shared__ unsigned smem[];
    unsigned* sK = smem;                       // [64][SKS]
    unsigned* sV = smem + 64 * SKS;            // [64][SVS]
    unsigned* sP = smem + 64 * SKS + 64 * SVS; // [128][SPS]

    const int tid = threadIdx.x;
    const int lane = tid & 31;
    const int w = tid >> 5;
    const int g = lane >> 2;
    const int t = lane & 3;

    const int bh = blockIdx.y;
    const int q0 = blockIdx.x * 128;

    // Q fragments for two 16-row groups (tf32, pre-scaled)
    unsigned qa[2][8][4];
#pragma unroll
    for (int mt = 0; mt < 2; mt++) {
        const unsigned* p0 = g_Qt + ((size_t)bh * SEQ + (q0 + w * 32 + mt * 16 + g)) * HD;
        const unsigned* p1 = p0 + 8 * HD;
#pragma unroll
        for (int kt = 0; kt < 8; kt++) {
            qa[mt][kt][0] = p0[8 * kt + t];
            qa[mt][kt][1] = p1[8 * kt + t];
            qa[mt][kt][2] = p0[8 * kt + t + 4];
            qa[mt][kt][3] = p1[8 * kt + t + 4];
        }
    }

    float o[2][8][4];
#pragma unroll
    for (int mt = 0; mt < 2; mt++)
#pragma unroll
        for (int nt = 0; nt < 8; nt++)
#pragma unroll
            for (int i = 0; i < 4; i++) o[mt][nt][i] = 0.f;
    float mx[2][2], l[2][2];
#pragma unroll
    for (int mt = 0; mt < 2; mt++) { mx[mt][0] = mx[mt][1] = -1e30f; l[mt][0] = l[mt][1] = 0.f; }

    const uint4* Ksrc = (const uint4*)(g_Kt + (size_t)bh * SEQ * HD);
    const uint4* Vsrc = (const uint4*)(g_Vt + (size_t)bh * SEQ * HD);

    for (int kv = 0; kv < SEQ / 64; kv++) {
        __syncthreads();
#pragma unroll
        for (int i = 0; i < 8; i++) {
            int idx = tid + i * 128;
            int r = idx >> 4, c4 = (idx & 15) * 4;
            *(uint4*)(sK + r * SKS + c4) = Ksrc[kv * 1024 + idx];
            *(uint4*)(sV + r * SVS + c4) = Vsrc[kv * 1024 + idx];
        }
        __syncthreads();

        // --- S = Q @ K^T for both row groups; K fragments loaded once ---
        float s[2][8][4];
#pragma unroll
        for (int mt = 0; mt < 2; mt++)
#pragma unroll
            for (int nt = 0; nt < 8; nt++)
#pragma unroll
                for (int i = 0; i < 4; i++) s[mt][nt][i] = 0.f;

#pragma unroll
        for (int kt = 0; kt < 8; kt++) {
#pragma unroll
            for (int nt = 0; nt < 8; nt++) {
                unsigned b0 = sK[(8 * nt + g) * SKS + 8 * kt + t];
                unsigned b1 = sK[(8 * nt + g) * SKS + 8 * kt + t + 4];
#pragma unroll
                for (int mt = 0; mt < 2; mt++)
                    mma_tf32(s[mt][nt], qa[mt][kt][0], qa[mt][kt][1],
                             qa[mt][kt][2], qa[mt][kt][3], b0, b1);
            }
        }

        // --- online softmax per row group; write P to smem ---
#pragma unroll
        for (int mt = 0; mt < 2; mt++) {
            float rx0 = -1e30f, rx1 = -1e30f;
#pragma unroll
            for (int nt = 0; nt < 8; nt++) {
                rx0 = fmaxf(rx0, fmaxf(s[mt][nt][0], s[mt][nt][1]));
                rx1 = fmaxf(rx1, fmaxf(s[mt][nt][2], s[mt][nt][3]));
            }
            rx0 = fmaxf(rx0, __shfl_xor_sync(0xffffffffu, rx0, 1));
            rx0 = fmaxf(rx0, __shfl_xor_sync(0xffffffffu, rx0, 2));
            rx1 = fmaxf(rx1, __shfl_xor_sync(0xffffffffu, rx1, 1));
            rx1 = fmaxf(rx1, __shfl_xor_sync(0xffffffffu, rx1, 2));

            float nm0 = fmaxf(mx[mt][0], rx0), nm1 = fmaxf(mx[mt][1], rx1);
            float c0 = exp2f(mx[mt][0] - nm0), c1 = exp2f(mx[mt][1] - nm1);
            mx[mt][0] = nm0; mx[mt][1] = nm1;

            float ps0 = 0.f, ps1 = 0.f;
            unsigned* pr0 = sP + (w * 32 + mt * 16 + g) * SPS;
            unsigned* pr1 = pr0 + 8 * SPS;
#pragma unroll
            for (int nt = 0; nt < 8; nt++) {
                float e0 = exp2f(s[mt][nt][0] - nm0);
                float e1 = exp2f(s[mt][nt][1] - nm0);
                float e2 = exp2f(s[mt][nt][2] - nm1);
                float e3 = exp2f(s[mt][nt][3] - nm1);
                ps0 += e0 + e1;
                ps1 += e2 + e3;
                *(uint2*)(pr0 + 8 * nt + 2 * t) = make_uint2(f2tf32(e0), f2tf32(e1));
                *(uint2*)(pr1 + 8 * nt + 2 * t) = make_uint2(f2tf32(e2), f2tf32(e3));
            }
            ps0 += __shfl_xor_sync(0xffffffffu, ps0, 1);
            ps0 += __shfl_xor_sync(0xffffffffu, ps0, 2);
            ps1 += __shfl_xor_sync(0xffffffffu, ps1, 1);
            ps1 += __shfl_xor_sync(0xffffffffu, ps1, 2);
            l[mt][0] = l[mt][0] * c0 + ps0;
            l[mt][1] = l[mt][1] * c1 + ps1;

#pragma unroll
            for (int nt = 0; nt < 8; nt++) {
                o[mt][nt][0] *= c0; o[mt][nt][1] *= c0;
                o[mt][nt][2] *= c1; o[mt][nt][3] *= c1;
            }
        }
        __syncwarp();

        // --- O += P @ V ; V fragments loaded once per (kt,nt) ---
#pragma unroll
        for (int kt = 0; kt < 8; kt++) {
            unsigned pa[2][4];
#pragma unroll
            for (int mt = 0; mt < 2; mt++) {
                const unsigned* pr0 = sP + (w * 32 + mt * 16 + g) * SPS;
                const unsigned* pr1 = pr0 + 8 * SPS;
                pa[mt][0] = pr0[8 * kt + t];
                pa[mt][1] = pr1[8 * kt + t];
                pa[mt][2] = pr0[8 * kt + t + 4];
                pa[mt][3] = pr1[8 * kt + t + 4];
            }
#pragma unroll
            for (int nt = 0; nt < 8; nt++) {
                unsigned b0 = sV[(8 * kt + t) * SVS + 8 * nt + g];
                unsigned b1 = sV[(8 * kt + t + 4) * SVS + 8 * nt + g];
#pragma unroll
                for (int mt = 0; mt < 2; mt++)
                    mma_tf32(o[mt][nt], pa[mt][0], pa[mt][1], pa[mt][2], pa[mt][3], b0, b1);
            }
        }
    }

    const int b = bh >> 4, h = bh & 15;
#pragma unroll
    for (int mt = 0; mt < 2; mt++) {
        const float inv0 = 1.f / l[mt][0], inv1 = 1.f / l[mt][1];
        const int r0 = q0 + w * 32 + mt * 16 + g;
        float* op0 = out2 + ((size_t)b * SEQ + r0) * CDIM + h * HD;
        float* op1 = op0 + (size_t)8 * CDIM;
#pragma unroll
        for (int nt = 0; nt < 8; nt++) {
            *(float2*)(op0 + 8 * nt + 2 * t) =
                make_float2(o[mt][nt][0] * inv0, o[mt][nt][1] * inv0);
            *(float2*)(op1 + 8 * nt + 2 * t) =
                make_float2(o[mt][nt][2] * inv1, o[mt][nt][3] * inv1);
        }
    }
}

// ---------------------------------------------------------------------------
// Kernel 3: proj GEMM. out = (att2 + f) @ W + b. Same structure as qkv_tc.
// ---------------------------------------------------------------------------
__global__ __launch_bounds__(128, 2) void proj_tc(const float* __restrict__ att2,
                                                  const float* __restrict__ F,
                                                  const float* __restrict__ W,
                                                  const float* __restrict__ bias,
                                                  float* __restrict__ out) {
    __shared__ unsigned sA[2][128][AST];
    __shared__ unsigned sB[2][16][BST];

    const int tid = threadIdx.x;
    const int lane = tid & 31;
    const int w = tid >> 5;
    const int g = lane >> 2, t = lane & 3;
    const int wm = w & 1, wn = w >> 1;

    const int m0 = blockIdx.y * 128;
    const int n0 = blockIdx.x * 128;

    float acc[4][8][4];
#pragma unroll
    for (int mt = 0; mt < 4; mt++)
#pragma unroll
        for (int nt = 0; nt < 8; nt++)
#pragma unroll
            for (int i = 0; i < 4; i++) acc[mt][nt][i] = 0.f;

    const float* aptr = att2 + (size_t)(m0 + tid) * CDIM;
    const float* fptr = F + (size_t)(m0 + tid) * CDIM;
    const int bk = tid >> 5, bn = 4 * (tid & 31);
    const float* bptr = W + (size_t)bk * CDIM + n0 + bn;

    float4 ra[4], rb[4];
#pragma unroll
    for (int i = 0; i < 4; i++) {
        float4 x = *(const float4*)(aptr + 4 * i);
        float4 y = *(const float4*)(fptr + 4 * i);
        ra[i] = make_float4(x.x + y.x, x.y + y.y, x.z + y.z, x.w + y.w);
        rb[i] = *(const float4*)(bptr + (size_t)(4 * i) * CDIM);
    }

    int buf = 0;
#pragma unroll
    for (int i = 0; i < 4; i++) {
        *(uint4*)&sA[0][tid][4 * i] = make_uint4(f2tf32(ra[i].x), f2tf32(ra[i].y),
                                                 f2tf32(ra[i].z), f2tf32(ra[i].w));
        *(uint4*)&sB[0][bk + 4 * i][bn] = make_uint4(f2tf32(rb[i].x), f2tf32(rb[i].y),
                                                     f2tf32(rb[i].z), f2tf32(rb[i].w));
    }
    __syncthreads();

    for (int k0 = 16; k0 <= CDIM; k0 += 16) {
        if (k0 < CDIM) {
#pragma unroll
            for (int i = 0; i < 4; i++) {
                float4 x = *(const float4*)(aptr + k0 + 4 * i);
                float4 y = *(const float4*)(fptr + k0 + 4 * i);
                ra[i] = make_float4(x.x + y.x, x.y + y.y, x.z + y.z, x.w + y.w);
                rb[i] = *(const float4*)(bptr + (size_t)(k0 + 4 * i) * CDIM);
            }
        }

#pragma unroll
        for (int kt = 0; kt < 2; kt++) {
            unsigned af[4][4];
#pragma unroll
            for (int mt = 0; mt < 4; mt++) {
                int mr = wm * 64 + mt * 16;
                af[mt][0] = sA[buf][mr + g][8 * kt + t];
                af[mt][1] = sA[buf][mr + g + 8][8 * kt + t];
                af[mt][2] = sA[buf][mr + g][8 * kt + t + 4];
                af[mt][3] = sA[buf][mr + g + 8][8 * kt + t + 4];
            }
#pragma unroll
            for (int nt = 0; nt < 8; nt++) {
                int nc = wn * 64 + nt * 8 + g;
                unsigned b0 = sB[buf][kt * 8 + t][nc];
                unsigned b1 = sB[buf][kt * 8 + t + 4][nc];
#pragma unroll
                for (int mt = 0; mt < 4; mt++)
                    mma_tf32(acc[mt][nt], af[mt][0], af[mt][1], af[mt][2], af[mt][3], b0, b1);
            }
        }

        if (k0 < CDIM) {
#pragma unroll
            for (int i = 0; i < 4; i++) {
                *(uint4*)&sA[buf ^ 1][tid][4 * i] =
                    make_uint4(f2tf32(ra[i].x), f2tf32(ra[i].y),
                               f2tf32(ra[i].z), f2tf32(ra[i].w));
                *(uint4*)&sB[buf ^ 1][bk + 4 * i][bn] =
                    make_uint4(f2tf32(rb[i].x), f2tf32(rb[i].y),
                               f2tf32(rb[i].z), f2tf32(rb[i].w));
            }
            __syncthreads();
            buf ^= 1;
        }
    }

#pragma unroll
    for (int mt = 0; mt < 4; mt++) {
#pragma unroll
        for (int nt = 0; nt < 8; nt++) {
            int col = n0 + wn * 64 + nt * 8 + 2 * t;
            float2 bb = *(const float2*)&bias[col];
            int row0 = m0 + wm * 64 + mt * 16 + g;
            float* p0 = out + (size_t)row0 * CDIM + col;
            float* p1 = out + (size_t)(row0 + 8) * CDIM + col;
            *(float2*)p0 = make_float2(acc[mt][nt][0] + bb.x, acc[mt][nt][1] + bb.y);
            *(float2*)p1 = make_float2(acc[mt][nt][2] + bb.x, acc[mt][nt][3] + bb.y);
        }
    }
}

extern "C" void kernel_launch(void* const* d_in, const int* in_sizes, int n_in,
                              void* d_out, int out_size) {
    const float* x     = (const float*)d_in[0];
    const float* f     = (const float*)d_in[1];
    const float* Wqkv  = (const float*)d_in[2];
    const float* Wproj = (const float*)d_in[3];
    const float* bproj = (const float*)d_in[4];
    float* out = (float*)d_out;

    const size_t half = (size_t)BATCH * SEQ * CDIM;
    float* att2;
    if ((size_t)out_size >= 2 * half) {
        att2 = out + half;
    } else {
        cudaGetSymbolAddress((void**)&att2, g_att_fallback);
    }

    cudaFuncSetAttribute(flash_attn_tc, cudaFuncAttributeMaxDynamicSharedMemorySize,
                         FLASH_SMEM);

    qkv_tc<<<dim3(QKVN / 128, ROWS / 128), 128>>>(x, Wqkv);
    flash_attn_tc<<<dim3(SEQ / 128, BHN), 128, FLASH_SMEM>>>(att2);
    proj_tc<<<dim3(CDIM / 128, ROWS / 128), 128>>>(att2, f, Wproj, bproj, out);
}